// round 9
// baseline (speedup 1.0000x reference)
#include <cuda_runtime.h>
#include <math.h>
#include <stdint.h>

// Problem constants
#define T_TOK 8192          // B*S tokens
#define DDIM  1024          // model dim
#define NEXP  8             // experts
#define TOPK  2
#define HDIM  4096          // FFN hidden per expert
#define PAIRS (T_TOK * TOPK)

// ---------------- device scratch (R1-proven) ----------------
__device__ int   g_cnt[NEXP];
__device__ int   g_fill[NEXP];
__device__ int   g_off[NEXP + 1];
__device__ int   g_topi[T_TOK * TOPK];
__device__ float g_topw[T_TOK * TOPK];
__device__ int   g_tok[PAIRS];
__device__ float g_gw[PAIRS];
__device__ int   g_oslot[PAIRS];
__device__ __align__(16) float g_h[(size_t)PAIRS * HDIM];   // 256 MB intermediate
__device__ __align__(16) float g_yp[(size_t)PAIRS * DDIM];  // 64 MB partial outputs

// ---------------- packed f32x2 helpers ----------------
__device__ __forceinline__ void ffma2(unsigned long long& d,
                                      unsigned long long a,
                                      unsigned long long b) {
    asm("fma.rn.f32x2 %0, %1, %2, %0;" : "+l"(d) : "l"(a), "l"(b));
}
__device__ __forceinline__ unsigned long long pack_dup(float x) {
    unsigned long long r;
    asm("mov.b64 %0, {%1, %1};" : "=l"(r) : "f"(x));
    return r;
}
__device__ __forceinline__ void unpack2(unsigned long long v, float& lo, float& hi) {
    asm("mov.b64 {%0, %1}, %2;" : "=f"(lo), "=f"(hi) : "l"(v));
}

// ---------------- small kernels (verbatim R1) ----------------
__global__ void zero_kernel() {
    int i = threadIdx.x;
    if (i < NEXP) { g_cnt[i] = 0; g_fill[i] = 0; }
}

__global__ void router_kernel(const float* __restrict__ x,
                              const float* __restrict__ Wg,
                              const float* __restrict__ bg) {
    int warp = (blockIdx.x * blockDim.x + threadIdx.x) >> 5;
    int lane = threadIdx.x & 31;
    if (warp >= T_TOK) return;
    const float* xr = x + (size_t)warp * DDIM;

    float acc[NEXP];
#pragma unroll
    for (int e = 0; e < NEXP; e++) acc[e] = 0.f;

    for (int d = lane; d < DDIM; d += 32) {
        float xv = xr[d];
        const float4* wg = (const float4*)(Wg + (size_t)d * NEXP);
        float4 w0 = wg[0], w1 = wg[1];
        acc[0] += xv * w0.x; acc[1] += xv * w0.y;
        acc[2] += xv * w0.z; acc[3] += xv * w0.w;
        acc[4] += xv * w1.x; acc[5] += xv * w1.y;
        acc[6] += xv * w1.z; acc[7] += xv * w1.w;
    }
#pragma unroll
    for (int e = 0; e < NEXP; e++) {
#pragma unroll
        for (int o = 16; o > 0; o >>= 1)
            acc[e] += __shfl_xor_sync(0xffffffffu, acc[e], o);
    }
    if (lane == 0) {
        float logit[NEXP];
        float m = -1e30f;
#pragma unroll
        for (int e = 0; e < NEXP; e++) { logit[e] = acc[e] + bg[e]; m = fmaxf(m, logit[e]); }
        float p[NEXP], s = 0.f;
#pragma unroll
        for (int e = 0; e < NEXP; e++) { p[e] = __expf(logit[e] - m); s += p[e]; }
        float inv = 1.f / s;
#pragma unroll
        for (int e = 0; e < NEXP; e++) p[e] *= inv;
        int i1 = 0; float v1 = p[0];
#pragma unroll
        for (int e = 1; e < NEXP; e++) if (p[e] > v1) { v1 = p[e]; i1 = e; }
        int i2 = -1; float v2 = -1.f;
#pragma unroll
        for (int e = 0; e < NEXP; e++) {
            if (e == i1) continue;
            if (p[e] > v2) { v2 = p[e]; i2 = e; }
        }
        g_topi[warp * 2 + 0] = i1; g_topw[warp * 2 + 0] = v1;
        g_topi[warp * 2 + 1] = i2; g_topw[warp * 2 + 1] = v2;
        atomicAdd(&g_cnt[i1], 1);
        atomicAdd(&g_cnt[i2], 1);
    }
}

__global__ void prefix_kernel() {
    if (threadIdx.x == 0) {
        int s = 0;
        g_off[0] = 0;
        for (int e = 0; e < NEXP; e++) { s += g_cnt[e]; g_off[e + 1] = s; }
    }
}

__global__ void scatter_kernel() {
    int t = blockIdx.x * blockDim.x + threadIdx.x;
    if (t >= T_TOK) return;
#pragma unroll
    for (int k = 0; k < TOPK; k++) {
        int e = g_topi[t * 2 + k];
        int pos = atomicAdd(&g_fill[e], 1);
        int slot = g_off[e] + pos;
        g_tok[slot] = t;
        g_gw[slot] = g_topw[t * 2 + k];
        g_oslot[slot] = t * 2 + k;
    }
}

__device__ __forceinline__ float gelu_exact(float v) {
    return 0.5f * v * (1.0f + erff(v * 0.70710678118654752f));
}

// ---------------- GEMM1: h = gelu(gather(x) @ W1[e] + b1[e]) ----------------
// R1 structure: 128x128 tile, BK=8, 256 threads, 8x8/thread.
// Inner product re-expressed as packed fma.rn.f32x2 (32 FFMA2 vs 64 FFMA per k).
__global__ __launch_bounds__(256) void gemm1_kernel(const float* __restrict__ x,
                                                    const float* __restrict__ W1,
                                                    const float* __restrict__ b1) {
    int e = blockIdx.z;
    int n_e = g_cnt[e];
    int row0 = blockIdx.y * 128;
    if (row0 >= n_e) return;
    int col0 = blockIdx.x * 128;
    int base = g_off[e];

    __shared__ __align__(16) float As[8][128];
    __shared__ __align__(16) float Bs[8][128];

    int tid = threadIdx.x;
    int arow = tid >> 1;
    int ahalf = (tid & 1) * 4;
    int grow = row0 + arow;
    int tokA = (grow < n_e) ? g_tok[base + grow] : -1;
    const float* aptr = (tokA >= 0) ? (x + (size_t)tokA * DDIM + ahalf) : nullptr;

    int bk = tid >> 5;
    int bcol = (tid & 31) * 4;
    const float* bptr = W1 + (size_t)e * DDIM * HDIM + (size_t)bk * HDIM + col0 + bcol;

    int tx = tid & 15, ty = tid >> 4;

    unsigned long long acc2[8][4];
#pragma unroll
    for (int i = 0; i < 8; i++)
#pragma unroll
        for (int j = 0; j < 4; j++) acc2[i][j] = 0ull;

    float4 aReg = aptr ? *(const float4*)aptr : make_float4(0.f, 0.f, 0.f, 0.f);
    float4 bReg = *(const float4*)bptr;

    const int KB = DDIM / 8;
    for (int kb = 0; kb < KB; kb++) {
        As[ahalf + 0][arow] = aReg.x;
        As[ahalf + 1][arow] = aReg.y;
        As[ahalf + 2][arow] = aReg.z;
        As[ahalf + 3][arow] = aReg.w;
        *(float4*)&Bs[bk][bcol] = bReg;
        __syncthreads();
        if (kb + 1 < KB) {
            aReg = aptr ? *(const float4*)(aptr + (kb + 1) * 8)
                        : make_float4(0.f, 0.f, 0.f, 0.f);
            bReg = *(const float4*)(bptr + (size_t)(kb + 1) * 8 * HDIM);
        }
#pragma unroll
        for (int kk = 0; kk < 8; kk++) {
            float a[8];
            *(float4*)(a)     = *(float4*)&As[kk][ty * 8];
            *(float4*)(a + 4) = *(float4*)&As[kk][ty * 8 + 4];
            unsigned long long b2[4];
            b2[0] = *(unsigned long long*)&Bs[kk][tx * 8 + 0];
            b2[1] = *(unsigned long long*)&Bs[kk][tx * 8 + 2];
            b2[2] = *(unsigned long long*)&Bs[kk][tx * 8 + 4];
            b2[3] = *(unsigned long long*)&Bs[kk][tx * 8 + 6];
            unsigned long long a2[8];
#pragma unroll
            for (int i = 0; i < 8; i++) a2[i] = pack_dup(a[i]);
#pragma unroll
            for (int i = 0; i < 8; i++)
#pragma unroll
                for (int j = 0; j < 4; j++)
                    ffma2(acc2[i][j], a2[i], b2[j]);
        }
        __syncthreads();
    }

#pragma unroll
    for (int i = 0; i < 8; i++) {
        int r = row0 + ty * 8 + i;
        if (r >= n_e) break;
        size_t slot = (size_t)(base + r);
#pragma unroll
        for (int j = 0; j < 4; j++) {
            int n = col0 + tx * 8 + j * 2;
            const float* bb = b1 + (size_t)e * HDIM + n;
            float lo, hi;
            unpack2(acc2[i][j], lo, hi);
            float2 v;
            v.x = gelu_exact(lo + bb[0]);
            v.y = gelu_exact(hi + bb[1]);
            *(float2*)&g_h[slot * HDIM + n] = v;
        }
    }
}

// ---------------- GEMM2: yp = gw * (h @ W2[e] + b2[e]) ----------------
__global__ __launch_bounds__(256) void gemm2_kernel(const float* __restrict__ W2,
                                                    const float* __restrict__ b2) {
    int e = blockIdx.z;
    int n_e = g_cnt[e];
    int row0 = blockIdx.y * 128;
    if (row0 >= n_e) return;
    int col0 = blockIdx.x * 128;
    int base = g_off[e];

    __shared__ __align__(16) float As[8][128];
    __shared__ __align__(16) float Bs[8][128];

    int tid = threadIdx.x;
    int arow = tid >> 1;
    int ahalf = (tid & 1) * 4;
    int grow = row0 + arow;
    bool avalid = (grow < n_e);
    const float* aptr = avalid ? (g_h + (size_t)(base + grow) * HDIM + ahalf) : nullptr;

    int bk = tid >> 5;
    int bcol = (tid & 31) * 4;
    const float* bptr = W2 + (size_t)e * HDIM * DDIM + (size_t)bk * DDIM + col0 + bcol;

    int tx = tid & 15, ty = tid >> 4;

    unsigned long long acc2[8][4];
#pragma unroll
    for (int i = 0; i < 8; i++)
#pragma unroll
        for (int j = 0; j < 4; j++) acc2[i][j] = 0ull;

    float4 aReg = aptr ? *(const float4*)aptr : make_float4(0.f, 0.f, 0.f, 0.f);
    float4 bReg = *(const float4*)bptr;

    const int KB = HDIM / 8;
    for (int kb = 0; kb < KB; kb++) {
        As[ahalf + 0][arow] = aReg.x;
        As[ahalf + 1][arow] = aReg.y;
        As[ahalf + 2][arow] = aReg.z;
        As[ahalf + 3][arow] = aReg.w;
        *(float4*)&Bs[bk][bcol] = bReg;
        __syncthreads();
        if (kb + 1 < KB) {
            aReg = aptr ? *(const float4*)(aptr + (kb + 1) * 8)
                        : make_float4(0.f, 0.f, 0.f, 0.f);
            bReg = *(const float4*)(bptr + (size_t)(kb + 1) * 8 * DDIM);
        }
#pragma unroll
        for (int kk = 0; kk < 8; kk++) {
            float a[8];
            *(float4*)(a)     = *(float4*)&As[kk][ty * 8];
            *(float4*)(a + 4) = *(float4*)&As[kk][ty * 8 + 4];
            unsigned long long b2v[4];
            b2v[0] = *(unsigned long long*)&Bs[kk][tx * 8 + 0];
            b2v[1] = *(unsigned long long*)&Bs[kk][tx * 8 + 2];
            b2v[2] = *(unsigned long long*)&Bs[kk][tx * 8 + 4];
            b2v[3] = *(unsigned long long*)&Bs[kk][tx * 8 + 6];
            unsigned long long a2[8];
#pragma unroll
            for (int i = 0; i < 8; i++) a2[i] = pack_dup(a[i]);
#pragma unroll
            for (int i = 0; i < 8; i++)
#pragma unroll
                for (int j = 0; j < 4; j++)
                    ffma2(acc2[i][j], a2[i], b2v[j]);
        }
        __syncthreads();
    }

#pragma unroll
    for (int i = 0; i < 8; i++) {
        int r = row0 + ty * 8 + i;
        if (r >= n_e) break;
        int slot = base + r;
        float gw = g_gw[slot];
        size_t obase = (size_t)g_oslot[slot] * DDIM;
#pragma unroll
        for (int j = 0; j < 4; j++) {
            int n = col0 + tx * 8 + j * 2;
            const float* bb = b2 + (size_t)e * DDIM + n;
            float lo, hi;
            unpack2(acc2[i][j], lo, hi);
            float2 v;
            v.x = gw * (lo + bb[0]);
            v.y = gw * (hi + bb[1]);
            *(float2*)&g_yp[obase + n] = v;
        }
    }
}

__global__ void combine_kernel(float* __restrict__ out) {
    int i = blockIdx.x * blockDim.x + threadIdx.x;   // float4 index
    const int NV = T_TOK * DDIM / 4;
    if (i >= NV) return;
    int t = i / (DDIM / 4);
    int d4 = i % (DDIM / 4);
    const float4* yp = (const float4*)g_yp;
    float4 a = yp[(size_t)(2 * t) * (DDIM / 4) + d4];
    float4 b = yp[(size_t)(2 * t + 1) * (DDIM / 4) + d4];
    float4 v;
    v.x = a.x + b.x; v.y = a.y + b.y; v.z = a.z + b.z; v.w = a.w + b.w;
    ((float4*)out)[i] = v;
}

// ---------------- launch ----------------
extern "C" void kernel_launch(void* const* d_in, const int* in_sizes, int n_in,
                              void* d_out, int out_size) {
    const float* x  = (const float*)d_in[0];
    const float* Wg = (const float*)d_in[1];
    const float* bg = (const float*)d_in[2];
    const float* W1 = (const float*)d_in[3];
    const float* b1 = (const float*)d_in[4];
    const float* W2 = (const float*)d_in[5];
    const float* b2 = (const float*)d_in[6];
    float* out = (float*)d_out;

    zero_kernel<<<1, 32>>>();
    router_kernel<<<T_TOK / 8, 256>>>(x, Wg, bg);   // 8 warps/block
    prefix_kernel<<<1, 1>>>();
    scatter_kernel<<<T_TOK / 256, 256>>>();

    dim3 g1(HDIM / 128, T_TOK / 128, NEXP);   // (32, 64, 8)
    gemm1_kernel<<<g1, 256>>>(x, W1, b1);

    dim3 g2(DDIM / 128, T_TOK / 128, NEXP);   // (8, 64, 8)
    gemm2_kernel<<<g2, 256>>>(W2, b2);

    combine_kernel<<<(T_TOK * DDIM / 4 + 255) / 256, 256>>>(out);
}

// round 10
// speedup vs baseline: 1.4662x; 1.4662x over previous
#include <cuda_runtime.h>
#include <math.h>
#include <stdint.h>

// Problem constants
#define T_TOK 8192          // B*S tokens
#define DDIM  1024          // model dim
#define NEXP  8             // experts
#define TOPK  2
#define HDIM  4096          // FFN hidden per expert
#define PAIRS (T_TOK * TOPK)

// ---------------- device scratch ----------------
__device__ int   g_cnt[NEXP];
__device__ int   g_fill[NEXP];
__device__ int   g_off[NEXP + 1];
__device__ int   g_topi[T_TOK * TOPK];
__device__ float g_topw[T_TOK * TOPK];
__device__ int   g_tok[PAIRS];
__device__ float g_gw[PAIRS];
__device__ __align__(16) float g_h[(size_t)PAIRS * HDIM];   // 256 MB intermediate

// ---------------- small kernels ----------------
__global__ void zero_out_kernel(float* __restrict__ out) {
    if (blockIdx.x == 0 && threadIdx.x < NEXP) {
        g_cnt[threadIdx.x] = 0;
        g_fill[threadIdx.x] = 0;
    }
    int i = blockIdx.x * blockDim.x + threadIdx.x;    // float4 idx
    const int NV = T_TOK * DDIM / 4;
    if (i < NV) ((float4*)out)[i] = make_float4(0.f, 0.f, 0.f, 0.f);
}

__global__ void router_kernel(const float* __restrict__ x,
                              const float* __restrict__ Wg,
                              const float* __restrict__ bg) {
    int warp = (blockIdx.x * blockDim.x + threadIdx.x) >> 5;
    int lane = threadIdx.x & 31;
    if (warp >= T_TOK) return;
    const float* xr = x + (size_t)warp * DDIM;

    float acc[NEXP];
#pragma unroll
    for (int e = 0; e < NEXP; e++) acc[e] = 0.f;

    for (int d = lane; d < DDIM; d += 32) {
        float xv = xr[d];
        const float4* wg = (const float4*)(Wg + (size_t)d * NEXP);
        float4 w0 = wg[0], w1 = wg[1];
        acc[0] += xv * w0.x; acc[1] += xv * w0.y;
        acc[2] += xv * w0.z; acc[3] += xv * w0.w;
        acc[4] += xv * w1.x; acc[5] += xv * w1.y;
        acc[6] += xv * w1.z; acc[7] += xv * w1.w;
    }
#pragma unroll
    for (int e = 0; e < NEXP; e++) {
#pragma unroll
        for (int o = 16; o > 0; o >>= 1)
            acc[e] += __shfl_xor_sync(0xffffffffu, acc[e], o);
    }
    if (lane == 0) {
        float logit[NEXP];
        float m = -1e30f;
#pragma unroll
        for (int e = 0; e < NEXP; e++) { logit[e] = acc[e] + bg[e]; m = fmaxf(m, logit[e]); }
        float p[NEXP], s = 0.f;
#pragma unroll
        for (int e = 0; e < NEXP; e++) { p[e] = __expf(logit[e] - m); s += p[e]; }
        float inv = 1.f / s;
#pragma unroll
        for (int e = 0; e < NEXP; e++) p[e] *= inv;
        int i1 = 0; float v1 = p[0];
#pragma unroll
        for (int e = 1; e < NEXP; e++) if (p[e] > v1) { v1 = p[e]; i1 = e; }
        int i2 = -1; float v2 = -1.f;
#pragma unroll
        for (int e = 0; e < NEXP; e++) {
            if (e == i1) continue;
            if (p[e] > v2) { v2 = p[e]; i2 = e; }
        }
        g_topi[warp * 2 + 0] = i1; g_topw[warp * 2 + 0] = v1;
        g_topi[warp * 2 + 1] = i2; g_topw[warp * 2 + 1] = v2;
        atomicAdd(&g_cnt[i1], 1);
        atomicAdd(&g_cnt[i2], 1);
    }
}

__global__ void prefix_kernel() {
    if (threadIdx.x == 0) {
        int s = 0;
        g_off[0] = 0;
        for (int e = 0; e < NEXP; e++) { s += g_cnt[e]; g_off[e + 1] = s; }
    }
}

__global__ void scatter_kernel() {
    int t = blockIdx.x * blockDim.x + threadIdx.x;
    if (t >= T_TOK) return;
#pragma unroll
    for (int k = 0; k < TOPK; k++) {
        int e = g_topi[t * 2 + k];
        int pos = atomicAdd(&g_fill[e], 1);
        int slot = g_off[e] + pos;
        g_tok[slot] = t;
        g_gw[slot] = g_topw[t * 2 + k];
    }
}

__device__ __forceinline__ float gelu_exact(float v) {
    return 0.5f * v * (1.0f + erff(v * 0.70710678118654752f));
}

// ---------------- GEMM1: h = gelu(gather(x) @ W1[e] + b1[e]) ----------------
// 128x128 tile, BK=8, 256 threads, 8x8/thread.
// Double-buffered smem, ONE __syncthreads per k-chunk, overlapped global prefetch.
__global__ __launch_bounds__(256) void gemm1_kernel(const float* __restrict__ x,
                                                    const float* __restrict__ W1,
                                                    const float* __restrict__ b1) {
    int e = blockIdx.z;
    int n_e = g_cnt[e];
    int row0 = blockIdx.y * 128;
    if (row0 >= n_e) return;
    int col0 = blockIdx.x * 128;
    int base = g_off[e];

    __shared__ __align__(16) float As[2][8][128];
    __shared__ __align__(16) float Bs[2][8][128];

    int tid = threadIdx.x;
    int arow = tid >> 1;
    int ahalf = (tid & 1) * 4;
    int grow = row0 + arow;
    int rc = (grow < n_e) ? grow : (n_e - 1);     // clamped gather (always valid)
    const float* aptr = x + (size_t)g_tok[base + rc] * DDIM + ahalf;

    int bk = tid >> 5;
    int bcol = (tid & 31) * 4;
    const float* bptr = W1 + (size_t)e * DDIM * HDIM + (size_t)bk * HDIM + col0 + bcol;

    int tx = tid & 15, ty = tid >> 4;

    float acc[8][8];
#pragma unroll
    for (int i = 0; i < 8; i++)
#pragma unroll
        for (int j = 0; j < 8; j++) acc[i][j] = 0.f;

    const int KB = DDIM / 8;

    // prologue: stage 0 -> smem buf0; prefetch stage 1 -> regs
    float4 aReg = *(const float4*)aptr;
    float4 bReg = *(const float4*)bptr;
    As[0][ahalf + 0][arow] = aReg.x;
    As[0][ahalf + 1][arow] = aReg.y;
    As[0][ahalf + 2][arow] = aReg.z;
    As[0][ahalf + 3][arow] = aReg.w;
    *(float4*)&Bs[0][bk][bcol] = bReg;
    aReg = *(const float4*)(aptr + 8);
    bReg = *(const float4*)(bptr + (size_t)8 * HDIM);
    __syncthreads();

    for (int kb = 0; kb < KB; kb++) {
        int buf = kb & 1;
        if (kb + 1 < KB) {
            // store prefetched stage kb+1 into idle buffer (safe: last read of it
            // finished before the barrier at end of iteration kb-1)
            As[buf ^ 1][ahalf + 0][arow] = aReg.x;
            As[buf ^ 1][ahalf + 1][arow] = aReg.y;
            As[buf ^ 1][ahalf + 2][arow] = aReg.z;
            As[buf ^ 1][ahalf + 3][arow] = aReg.w;
            *(float4*)&Bs[buf ^ 1][bk][bcol] = bReg;
            if (kb + 2 < KB) {
                aReg = *(const float4*)(aptr + (kb + 2) * 8);
                bReg = *(const float4*)(bptr + (size_t)(kb + 2) * 8 * HDIM);
            }
        }
#pragma unroll
        for (int kk = 0; kk < 8; kk++) {
            float a[8], b[8];
            *(float4*)(a)     = *(float4*)&As[buf][kk][ty * 8];
            *(float4*)(a + 4) = *(float4*)&As[buf][kk][ty * 8 + 4];
            *(float4*)(b)     = *(float4*)&Bs[buf][kk][tx * 8];
            *(float4*)(b + 4) = *(float4*)&Bs[buf][kk][tx * 8 + 4];
#pragma unroll
            for (int i = 0; i < 8; i++)
#pragma unroll
                for (int j = 0; j < 8; j++) acc[i][j] += a[i] * b[j];
        }
        __syncthreads();
    }

#pragma unroll
    for (int i = 0; i < 8; i++) {
        int r = row0 + ty * 8 + i;
        if (r >= n_e) break;
        size_t slot = (size_t)(base + r);
#pragma unroll
        for (int j = 0; j < 8; j += 4) {
            int n = col0 + tx * 8 + j;
            const float* bb = b1 + (size_t)e * HDIM + n;
            float4 v;
            v.x = gelu_exact(acc[i][j + 0] + bb[0]);
            v.y = gelu_exact(acc[i][j + 1] + bb[1]);
            v.z = gelu_exact(acc[i][j + 2] + bb[2]);
            v.w = gelu_exact(acc[i][j + 3] + bb[3]);
            *(float4*)&g_h[slot * HDIM + n] = v;
        }
    }
}

// ---------------- GEMM2: out[tok] += gw * (h @ W2[e] + b2[e])  (fused combine) ----------------
__global__ __launch_bounds__(256) void gemm2_kernel(const float* __restrict__ W2,
                                                    const float* __restrict__ b2,
                                                    float* __restrict__ out) {
    int e = blockIdx.z;
    int n_e = g_cnt[e];
    int row0 = blockIdx.y * 128;
    if (row0 >= n_e) return;
    int col0 = blockIdx.x * 128;
    int base = g_off[e];

    __shared__ __align__(16) float As[2][8][128];
    __shared__ __align__(16) float Bs[2][8][128];

    int tid = threadIdx.x;
    int arow = tid >> 1;
    int ahalf = (tid & 1) * 4;
    int grow = row0 + arow;
    int rc = (grow < n_e) ? grow : (n_e - 1);
    const float* aptr = g_h + (size_t)(base + rc) * HDIM + ahalf;

    int bk = tid >> 5;
    int bcol = (tid & 31) * 4;
    const float* bptr = W2 + (size_t)e * HDIM * DDIM + (size_t)bk * DDIM + col0 + bcol;

    int tx = tid & 15, ty = tid >> 4;

    float acc[8][8];
#pragma unroll
    for (int i = 0; i < 8; i++)
#pragma unroll
        for (int j = 0; j < 8; j++) acc[i][j] = 0.f;

    const int KB = HDIM / 8;

    float4 aReg = *(const float4*)aptr;
    float4 bReg = *(const float4*)bptr;
    As[0][ahalf + 0][arow] = aReg.x;
    As[0][ahalf + 1][arow] = aReg.y;
    As[0][ahalf + 2][arow] = aReg.z;
    As[0][ahalf + 3][arow] = aReg.w;
    *(float4*)&Bs[0][bk][bcol] = bReg;
    aReg = *(const float4*)(aptr + 8);
    bReg = *(const float4*)(bptr + (size_t)8 * DDIM);
    __syncthreads();

    for (int kb = 0; kb < KB; kb++) {
        int buf = kb & 1;
        if (kb + 1 < KB) {
            As[buf ^ 1][ahalf + 0][arow] = aReg.x;
            As[buf ^ 1][ahalf + 1][arow] = aReg.y;
            As[buf ^ 1][ahalf + 2][arow] = aReg.z;
            As[buf ^ 1][ahalf + 3][arow] = aReg.w;
            *(float4*)&Bs[buf ^ 1][bk][bcol] = bReg;
            if (kb + 2 < KB) {
                aReg = *(const float4*)(aptr + (kb + 2) * 8);
                bReg = *(const float4*)(bptr + (size_t)(kb + 2) * 8 * DDIM);
            }
        }
#pragma unroll
        for (int kk = 0; kk < 8; kk++) {
            float a[8], b[8];
            *(float4*)(a)     = *(float4*)&As[buf][kk][ty * 8];
            *(float4*)(a + 4) = *(float4*)&As[buf][kk][ty * 8 + 4];
            *(float4*)(b)     = *(float4*)&Bs[buf][kk][tx * 8];
            *(float4*)(b + 4) = *(float4*)&Bs[buf][kk][tx * 8 + 4];
#pragma unroll
            for (int i = 0; i < 8; i++)
#pragma unroll
                for (int j = 0; j < 8; j++) acc[i][j] += a[i] * b[j];
        }
        __syncthreads();
    }

    // fused combine: out[token] += gw * (acc + bias). Each output element gets
    // exactly TOPK=2 commutative fp32 adds -> bitwise deterministic.
#pragma unroll
    for (int i = 0; i < 8; i++) {
        int r = row0 + ty * 8 + i;
        if (r >= n_e) break;
        int slot = base + r;
        float gw = g_gw[slot];
        float* op = out + (size_t)g_tok[slot] * DDIM;
#pragma unroll
        for (int j = 0; j < 8; j++) {
            int n = col0 + tx * 8 + j;
            atomicAdd(op + n, gw * (acc[i][j] + b2[e * DDIM + n]));
        }
    }
}

// ---------------- launch ----------------
extern "C" void kernel_launch(void* const* d_in, const int* in_sizes, int n_in,
                              void* d_out, int out_size) {
    const float* x  = (const float*)d_in[0];
    const float* Wg = (const float*)d_in[1];
    const float* bg = (const float*)d_in[2];
    const float* W1 = (const float*)d_in[3];
    const float* b1 = (const float*)d_in[4];
    const float* W2 = (const float*)d_in[5];
    const float* b2 = (const float*)d_in[6];
    float* out = (float*)d_out;

    zero_out_kernel<<<(T_TOK * DDIM / 4 + 255) / 256, 256>>>(out);
    router_kernel<<<T_TOK / 8, 256>>>(x, Wg, bg);   // 8 warps/block
    prefix_kernel<<<1, 1>>>();
    scatter_kernel<<<T_TOK / 256, 256>>>();

    dim3 g1(HDIM / 128, PAIRS / 128, NEXP);   // (32, 128, 8) — covers any skew
    gemm1_kernel<<<g1, 256>>>(x, W1, b1);

    dim3 g2(DDIM / 128, PAIRS / 128, NEXP);   // (8, 128, 8)
    gemm2_kernel<<<g2, 256>>>(W2, b2, out);
}